// round 1
// baseline (speedup 1.0000x reference)
#include <cuda_runtime.h>
#include <cstdint>

// Problem constants
#define NUM_USERS 100000
#define NUM_ITEMS 100000
#define EMB_K 6
#define BATCH 2048

#define N4 (NUM_USERS / 4)       // 25000 float4 per row
#define ROWS_PER_BLOCK 8
#define GEMV_THREADS 256

// Scratch for U_emb [BATCH][EMB_K] and int64-detection flag
__device__ float g_Uemb[BATCH * EMB_K];
__device__ int   g_is64;

// ---------------------------------------------------------------------------
// Detect whether x_item buffer is int64 or int32.
// Reads only the first 8192 bytes (safe for both layouts: int32 buffer is
// exactly 8192 bytes, int64 buffer is 16384 bytes).
// If int64 (values in [0,1e5)), every high word of the first 1024 entries is 0.
// ---------------------------------------------------------------------------
__global__ void detect_idx_kernel(const unsigned int* __restrict__ p) {
    __shared__ int any_nz;
    if (threadIdx.x == 0) any_nz = 0;
    __syncthreads();
    for (int b = threadIdx.x; b < 1024; b += blockDim.x) {
        if (p[2 * b + 1] != 0u) any_nz = 1;   // benign race, all write 1
    }
    __syncthreads();
    if (threadIdx.x == 0) g_is64 = any_nz ? 0 : 1;
}

// ---------------------------------------------------------------------------
// Main streaming GEMV: U_emb[b][k] = sum_i x_user[b][i] * W_w[k][i]
// Each block handles 8 batch rows across the full 100000-wide reduction.
// W float4s are loaded once per column step and reused across the 8 rows
// (register-level reuse -> W L2 traffic stays small).
// ---------------------------------------------------------------------------
__global__ __launch_bounds__(GEMV_THREADS)
void user_emb_kernel(const float4* __restrict__ x_user4,
                     const float4* __restrict__ Ww4) {
    const int row0 = blockIdx.x * ROWS_PER_BLOCK;
    const int tid  = threadIdx.x;

    float acc[ROWS_PER_BLOCK][EMB_K];
#pragma unroll
    for (int r = 0; r < ROWS_PER_BLOCK; r++)
#pragma unroll
        for (int k = 0; k < EMB_K; k++)
            acc[r][k] = 0.0f;

    for (int i4 = tid; i4 < N4; i4 += GEMV_THREADS) {
        float4 w[EMB_K];
#pragma unroll
        for (int k = 0; k < EMB_K; k++)
            w[k] = __ldg(&Ww4[k * N4 + i4]);

#pragma unroll
        for (int r = 0; r < ROWS_PER_BLOCK; r++) {
            const float4 x = __ldg(&x_user4[(size_t)(row0 + r) * N4 + i4]);
#pragma unroll
            for (int k = 0; k < EMB_K; k++) {
                acc[r][k] = fmaf(x.x, w[k].x, acc[r][k]);
                acc[r][k] = fmaf(x.y, w[k].y, acc[r][k]);
                acc[r][k] = fmaf(x.z, w[k].z, acc[r][k]);
                acc[r][k] = fmaf(x.w, w[k].w, acc[r][k]);
            }
        }
    }

    // Reduce across the block: warp shuffle, then cross-warp via smem.
    __shared__ float sred[GEMV_THREADS / 32][ROWS_PER_BLOCK * EMB_K];
    const int lane = tid & 31;
    const int warp = tid >> 5;

#pragma unroll
    for (int r = 0; r < ROWS_PER_BLOCK; r++) {
#pragma unroll
        for (int k = 0; k < EMB_K; k++) {
            float v = acc[r][k];
#pragma unroll
            for (int off = 16; off > 0; off >>= 1)
                v += __shfl_down_sync(0xffffffffu, v, off);
            if (lane == 0) sred[warp][r * EMB_K + k] = v;
        }
    }
    __syncthreads();

    if (tid < ROWS_PER_BLOCK * EMB_K) {
        float s = 0.0f;
#pragma unroll
        for (int w2 = 0; w2 < GEMV_THREADS / 32; w2++)
            s += sred[w2][tid];
        const int r = tid / EMB_K;
        const int k = tid % EMB_K;
        g_Uemb[(size_t)(row0 + r) * EMB_K + k] = s;
    }
}

// ---------------------------------------------------------------------------
// Epilogue: item gather + tiny MLP (12 -> 16 relu -> 8 relu -> concat 1 -> 1)
// One thread per batch element.
// ---------------------------------------------------------------------------
__global__ __launch_bounds__(256)
void mlp_kernel(const void* __restrict__ x_item,
                const float* __restrict__ H_w,
                const float* __restrict__ W1, const float* __restrict__ b1,
                const float* __restrict__ W2, const float* __restrict__ b2,
                const float* __restrict__ W3,
                float* __restrict__ out) {
    __shared__ float sW1[16 * 12], sb1[16], sW2[8 * 16], sb2[8], sW3[9];

    const int tid = threadIdx.x;
    if (tid < 16 * 12) sW1[tid] = W1[tid];
    if (tid < 16)      sb1[tid] = b1[tid];
    if (tid < 8 * 16)  sW2[tid] = W2[tid];
    if (tid < 8)       sb2[tid] = b2[tid];
    if (tid < 9)       sW3[tid] = W3[tid];
    __syncthreads();

    const int b = blockIdx.x * blockDim.x + tid;
    if (b >= BATCH) return;

    long long idx;
    if (g_is64) idx = ((const long long*)x_item)[b];
    else        idx = (long long)(((const int*)x_item)[b]);

    float z[12];
#pragma unroll
    for (int k = 0; k < EMB_K; k++)
        z[k] = g_Uemb[(size_t)b * EMB_K + k];
#pragma unroll
    for (int k = 0; k < EMB_K; k++)
        z[EMB_K + k] = __ldg(&H_w[(size_t)k * NUM_ITEMS + idx]);

    float h1[16];
#pragma unroll
    for (int j = 0; j < 16; j++) {
        float s = sb1[j];
#pragma unroll
        for (int i = 0; i < 12; i++)
            s = fmaf(z[i], sW1[j * 12 + i], s);
        h1[j] = fmaxf(s, 0.0f);
    }

    float h2[8];
#pragma unroll
    for (int j = 0; j < 8; j++) {
        float s = sb2[j];
#pragma unroll
        for (int i = 0; i < 16; i++)
            s = fmaf(h1[i], sW2[j * 16 + i], s);
        h2[j] = fmaxf(s, 0.0f);
    }

    float o = sW3[8];   // ones-column term
#pragma unroll
    for (int i = 0; i < 8; i++)
        o = fmaf(h2[i], sW3[i], o);

    out[b] = o;
}

// ---------------------------------------------------------------------------
// Launch
// ---------------------------------------------------------------------------
extern "C" void kernel_launch(void* const* d_in, const int* in_sizes, int n_in,
                              void* d_out, int out_size) {
    const float* x_user = (const float*)d_in[0];
    const void*  x_item = d_in[1];
    // const float* W_w  = (const float*)d_in[2];
    const float* H_w    = (const float*)d_in[3];
    const float* W1     = (const float*)d_in[4];
    const float* b1     = (const float*)d_in[5];
    const float* W2     = (const float*)d_in[6];
    const float* b2     = (const float*)d_in[7];
    const float* W3     = (const float*)d_in[8];
    float* out          = (float*)d_out;

    detect_idx_kernel<<<1, 256>>>((const unsigned int*)x_item);

    user_emb_kernel<<<BATCH / ROWS_PER_BLOCK, GEMV_THREADS>>>(
        (const float4*)x_user, (const float4*)d_in[2]);

    mlp_kernel<<<(BATCH + 255) / 256, 256>>>(
        x_item, H_w, W1, b1, W2, b2, W3, out);
}